// round 13
// baseline (speedup 1.0000x reference)
#include <cuda_runtime.h>
#include <cuda_fp16.h>
#include <cstdint>

#define DIM 256
#define MATSZ (DIM*DIM)
#define NPOS 2048
#define NITEMS (NPOS*4)
#define PGRID 148
#define DEPTH 4
#define LDEPTH 8
#define BT 8192                 // B tile: 128 rows * 64B
#define PITCH 129

#define SM_EXPM  (DEPTH*20480)           // MW=1,NPROD=3: 2*2048 + 2*8192
#define SM_TAB1  (DEPTH*18432)           // MW=1,NPROD=2: 2048 + 2*8192
#define SM_TAB2  (DEPTH*20480)           // MW=2,NPROD=2: 4096 + 2*8192
#define SM_LEAF  (LDEPTH*16384 + 2048)   // stages + meta

using f16 = __half;

// ---------------- static device scratch --------------------------------------
__device__ f16 g_eAh[2*MATSZ], g_eAl[2*MATSZ];
__device__ f16 g_TAh[2][2*MATSZ], g_TAl[2][2*MATSZ];
__device__ f16 g_TBh[2][2*MATSZ], g_TBl[2][2*MATSZ];
__device__ f16 g_tabAh[510*MATSZ];                     // A-layout hi (all levels)
__device__ f16 g_tabBh[510*MATSZ], g_tabBl[510*MATSZ]; // B-layout; lo used only lvl-1

// ---------------- helpers -----------------------------------------------------
__device__ __forceinline__ uint32_t smem_u32(const void* p) {
    uint32_t a;
    asm("{ .reg .u64 t; cvta.to.shared.u64 t, %1; cvt.u32.u64 %0, t; }" : "=r"(a) : "l"(p));
    return a;
}
__device__ __forceinline__ void ldm4(uint32_t a[4], uint32_t addr) {
    asm volatile("ldmatrix.sync.aligned.m8n8.x4.shared.b16 {%0,%1,%2,%3}, [%4];"
                 : "=r"(a[0]), "=r"(a[1]), "=r"(a[2]), "=r"(a[3]) : "r"(addr));
}
__device__ __forceinline__ void mma16816(float c[4], const uint32_t a[4],
                                         uint32_t b0, uint32_t b1) {
    asm volatile("mma.sync.aligned.m16n8k16.row.col.f32.f16.f16.f32 "
                 "{%0,%1,%2,%3}, {%4,%5,%6,%7}, {%8,%9}, {%0,%1,%2,%3};"
                 : "+f"(c[0]), "+f"(c[1]), "+f"(c[2]), "+f"(c[3])
                 : "r"(a[0]), "r"(a[1]), "r"(a[2]), "r"(a[3]), "r"(b0), "r"(b1));
}
__device__ __forceinline__ void cp16(uint32_t s, const void* g) {
    asm volatile("cp.async.cg.shared.global [%0], [%1], 16;" :: "r"(s), "l"(g));
}
__device__ __forceinline__ void cp_commit() {
    asm volatile("cp.async.commit_group;" ::: "memory");
}
template<int N>
__device__ __forceinline__ void cp_wait() {
    asm volatile("cp.async.wait_group %0;" :: "n"(N) : "memory");
}
__device__ __forceinline__ uint32_t swz(uint32_t row, uint32_t byteInRow) {
    uint32_t chunk = byteInRow >> 4;
    return row * 64u + ((chunk ^ ((row >> 1) & 3u)) << 4) + (byteInRow & 15u);
}
__device__ __forceinline__ uint32_t pack_hi(float f0, float f1, uint32_t& lo) {
    f16 h0 = __float2half(f0), h1 = __float2half(f1);
    f16 l0 = __float2half(f0 - __half2float(h0));
    f16 l1 = __float2half(f1 - __half2float(h1));
    __half2 hh = __halves2half2(h0, h1);
    __half2 ll = __halves2half2(l0, l1);
    lo = *(uint32_t*)&ll;
    return *(uint32_t*)&hh;
}

// ---------------- templated chunk MMA ----------------------------------------
template<int NPROD>
__device__ __forceinline__ void mma_chunk(uint32_t aBase, uint32_t aLo,
                                          uint32_t bBase, uint32_t bLo,
                                          int lane, int m0w, int n0w, float acc[2][4][4])
{
    #pragma unroll
    for (int s = 0; s < 2; ++s) {
        uint32_t ah[2][4], al[2][4], bh[2][4], bl[2][4];
        #pragma unroll
        for (int mt = 0; mt < 2; ++mt) {
            const uint32_t off = swz((uint32_t)(m0w + mt * 16 + (lane & 15)),
                                     (uint32_t)(s * 32 + ((lane & 16) ? 16 : 0)));
            ldm4(ah[mt], aBase + off);
            if (NPROD == 3) ldm4(al[mt], aLo + off);
        }
        #pragma unroll
        for (int nt = 0; nt < 2; ++nt) {
            const uint32_t off = swz((uint32_t)(n0w + nt * 16 + (lane & 7) + ((lane & 16) ? 8 : 0)),
                                     (uint32_t)(s * 32 + ((lane & 8) ? 16 : 0)));
            ldm4(bh[nt], bBase + off);
            if (NPROD >= 2) ldm4(bl[nt], bLo + off);
        }
        #pragma unroll
        for (int mt = 0; mt < 2; ++mt)
            #pragma unroll
            for (int nb = 0; nb < 4; ++nb) {
                const uint32_t b0h = bh[nb >> 1][(nb & 1) * 2];
                const uint32_t b1h = bh[nb >> 1][(nb & 1) * 2 + 1];
                mma16816(acc[mt][nb], ah[mt], b0h, b1h);
                if (NPROD >= 2)
                    mma16816(acc[mt][nb], ah[mt],
                             bl[nb >> 1][(nb & 1) * 2], bl[nb >> 1][(nb & 1) * 2 + 1]);
                if (NPROD == 3)
                    mma16816(acc[mt][nb], al[mt], b0h, b1h);
            }
    }
}

// ---------------- templated pipelined GEMM ------------------------------------
template<int MW, int NPROD>
__device__ __forceinline__ void gemm_run(
    const f16* __restrict__ Ah, const f16* __restrict__ Al,
    const f16* __restrict__ Bh, const f16* __restrict__ Bl,
    float acc[2][4][4])
{
    constexpr int MTILE  = 32 * MW;
    constexpr int NTHR   = 128 * MW;
    constexpr int ATILEB = MTILE * 64;
    constexpr int NA = (NPROD == 3) ? 2 : 1;
    constexpr int NB = (NPROD >= 2) ? 2 : 1;
    constexpr uint32_t STG = (uint32_t)(NA * ATILEB + NB * BT);

    extern __shared__ char sm[];
    const uint32_t smb = smem_u32(sm);
    const int tid = threadIdx.x, lane = tid & 31, wid = tid >> 5;
    const int m0w = (wid % MW) * 32, n0w = (wid / MW) * 32;
    const int lr = tid >> 2, cc = tid & 3;
    const uint32_t sdr = swz((uint32_t)lr, (uint32_t)cc * 16u);

    #pragma unroll
    for (int mt = 0; mt < 2; ++mt)
        #pragma unroll
        for (int nb = 0; nb < 4; ++nb)
            #pragma unroll
            for (int q = 0; q < 4; ++q) acc[mt][nb][q] = 0.0f;

    auto issue = [&](int c) {
        const uint32_t st = smb + (uint32_t)(c & (DEPTH - 1)) * STG;
        {
            const size_t go = (size_t)lr * DIM + c * 32 + cc * 8;
            cp16(st + sdr, Ah + go);
            if (NPROD == 3) cp16(st + sdr + ATILEB, Al + go);
        }
        #pragma unroll
        for (int rr = 0; rr < 128; rr += NTHR / 4) {
            const int r = lr + rr;
            const uint32_t sd = st + (uint32_t)(NA * ATILEB) + swz((uint32_t)r, (uint32_t)cc * 16u);
            const size_t go = (size_t)r * DIM + c * 32 + cc * 8;
            cp16(sd, Bh + go);
            if (NPROD >= 2) cp16(sd + BT, Bl + go);
        }
    };

    #pragma unroll
    for (int p = 0; p < DEPTH - 1; ++p) { issue(p); cp_commit(); }

    for (int c = 0; c < 8; ++c) {
        cp_wait<DEPTH - 2>();
        __syncthreads();
        if (c + DEPTH - 1 < 8) issue(c + DEPTH - 1);
        cp_commit();
        const uint32_t st = smb + (uint32_t)(c & (DEPTH - 1)) * STG;
        mma_chunk<NPROD>(st, st + ATILEB, st + NA * ATILEB, st + NA * ATILEB + BT,
                         lane, m0w, n0w, acc);
    }
}

// ---------------- templated staged epilogue -----------------------------------
template<int MW>
__device__ __forceinline__ void epi_split(float acc[2][4][4], float alpha, int addI,
                                          int mo, int no,
                                          f16* __restrict__ oAh, f16* __restrict__ oAl,
                                          f16* __restrict__ oBh, f16* __restrict__ oBl)
{
    extern __shared__ char sm[];
    float* sf = (float*)sm;
    const int tid = threadIdx.x, lane = tid & 31, wid = tid >> 5;
    const int m0w = (wid % MW) * 32, n0w = (wid / MW) * 32;
    const int r0 = lane >> 2, cq = (lane & 3) * 2;

    __syncthreads();
    #pragma unroll
    for (int mt = 0; mt < 2; ++mt)
        #pragma unroll
        for (int half = 0; half < 2; ++half) {
            const int row = m0w + mt * 16 + r0 + half * 8;
            const int gr = mo + row;
            #pragma unroll
            for (int nb = 0; nb < 4; ++nb) {
                const int col = n0w + nb * 8 + cq;
                const int gc = no + col;
                float v0 = alpha * acc[mt][nb][half * 2 + 0];
                float v1 = alpha * acc[mt][nb][half * 2 + 1];
                if (addI) {
                    if (gr == gc)     v0 += 1.0f;
                    if (gr == gc + 1) v1 += 1.0f;
                }
                sf[row * PITCH + col]     = v0;
                sf[row * PITCH + col + 1] = v1;
            }
        }
    __syncthreads();

    if (oAh) {
        const int r = tid >> 2, c0 = (tid & 3) * 32;
        uint32_t hv[16], lv[16];
        #pragma unroll
        for (int j = 0; j < 16; ++j)
            hv[j] = pack_hi(sf[r * PITCH + c0 + 2*j], sf[r * PITCH + c0 + 2*j + 1], lv[j]);
        uint4* dh = (uint4*)(oAh + (size_t)(mo + r) * DIM + no + c0);
        #pragma unroll
        for (int q = 0; q < 4; ++q)
            dh[q] = make_uint4(hv[4*q], hv[4*q+1], hv[4*q+2], hv[4*q+3]);
        if (oAl) {
            uint4* dl = (uint4*)(oAl + (size_t)(mo + r) * DIM + no + c0);
            #pragma unroll
            for (int q = 0; q < 4; ++q)
                dl[q] = make_uint4(lv[4*q], lv[4*q+1], lv[4*q+2], lv[4*q+3]);
        }
    }
    {
        const int c = tid & 127, rg = tid >> 7;
        const int rb = rg * 32;
        uint32_t hv[16], lv[16];
        #pragma unroll
        for (int j = 0; j < 16; ++j)
            hv[j] = pack_hi(sf[(rb + 2*j) * PITCH + c], sf[(rb + 2*j + 1) * PITCH + c], lv[j]);
        uint4* dh = (uint4*)(oBh + (size_t)(no + c) * DIM + mo + rb);
        #pragma unroll
        for (int q = 0; q < 4; ++q)
            dh[q] = make_uint4(hv[4*q], hv[4*q+1], hv[4*q+2], hv[4*q+3]);
        if (oBl) {
            uint4* dl = (uint4*)(oBl + (size_t)(no + c) * DIM + mo + rb);
            #pragma unroll
            for (int q = 0; q < 4; ++q)
                dl[q] = make_uint4(lv[4*q], lv[4*q+1], lv[4*q+2], lv[4*q+3]);
        }
    }
    __syncthreads();
}

// ---------------- kernels -----------------------------------------------------
// A = skew^T/16 ; seed T = I + A/4 (Taylor d=4, 4 squarings)
__global__ void k_skew(const float* __restrict__ prim, f16* TBh, f16* TBl)
{
    int idx = blockIdx.x * blockDim.x + threadIdx.x;
    if (idx >= 2 * MATSZ) return;
    int b = idx >> 16, ij = idx & 65535, i = ij >> 8, j = ij & 255;
    float a = (prim[(size_t)b * MATSZ + (size_t)j * DIM + i] -
               prim[(size_t)b * MATSZ + (size_t)i * DIM + j]) * 0.0625f;
    f16 h = __float2half(a);
    g_eAh[idx] = h;
    g_eAl[idx] = __float2half(a - __half2float(h));
    float d = (i == j) ? 1.0f : 0.0f;
    float tb = d - a * 0.25f;
    f16 th = __float2half(tb);
    TBh[idx] = th;
    TBl[idx] = __float2half(tb - __half2float(th));
}

// expm round: MW=1, NPROD=3. grid (2, 8, 2), block 128.
__global__ __launch_bounds__(128, 1)
void k_gemm_split(const f16* Ah, const f16* Al, const f16* Bh, const f16* Bl,
                  f16* oAh, f16* oAl, f16* oBh, f16* oBl, float alpha, int addI)
{
    const size_t off = (size_t)blockIdx.z * MATSZ;
    const int mo = blockIdx.y * 32, no = blockIdx.x * 128;
    float acc[2][4][4];
    gemm_run<1, 3>(Ah + off + (size_t)mo * DIM, Al + off + (size_t)mo * DIM,
                   Bh + off + (size_t)no * DIM, Bl + off + (size_t)no * DIM, acc);
    epi_split<1>(acc, alpha, addI, mo, no,
                 oAh ? oAh + off : nullptr, oAl ? oAl + off : nullptr,
                 oBh + off, oBl ? oBl + off : nullptr);
}

// table level build: NPROD=2 (A hi only, B = parent split), MW templated.
template<int MW>
__global__ __launch_bounds__(128 * MW, (MW == 1) ? 4 : 2)
void k_tab(int lvl)
{
    const int c = blockIdx.z;
    const int lb = lvl - 1;
    const size_t aoff = (size_t)(((1 << lb) - 2) + (c & ((1 << lb) - 1))) * MATSZ;
    const size_t boff = (size_t)(c >> lb) * MATSZ;
    const size_t ooff = (size_t)(((1 << lvl) - 2) + c) * MATSZ;
    const int mo = blockIdx.y * (32 * MW), no = blockIdx.x * 128;
    float acc[2][4][4];
    gemm_run<MW, 2>(g_tabAh + aoff + (size_t)mo * DIM, nullptr,
                    g_tabBh + boff + (size_t)no * DIM,
                    g_tabBl + boff + (size_t)no * DIM, acc);
    epi_split<MW>(acc, 1.0f, 0, mo, no,
                  g_tabAh + ooff, nullptr, g_tabBh + ooff, nullptr);
}

// ---------------- persistent leaf kernel (pairwise chunks) --------------------
__global__ __launch_bounds__(512, 1)
void k_leaf(const int* __restrict__ unique, float* __restrict__ out)
{
    extern __shared__ char sm[];
    const uint32_t smb = smem_u32(sm);
    uint4* metaM = (uint4*)(sm + LDEPTH * 16384);
    uint4* metaC = metaM + 60;
    __shared__ int cntM, cntC;
    const int tid = threadIdx.x, lane = tid & 31, wid = tid >> 5;
    const int m0w = (wid & 3) * 32, n0w = (wid >> 2) * 32;
    const int bid = blockIdx.x;

    if (tid == 0) { cntM = 0; cntC = 0; }
    __syncthreads();

    {
        const int w = bid + tid * PGRID;
        if (w < NITEMS) {
            const int n = w >> 2, tile = w & 3;
            const unsigned p = (unsigned)unique[n];
            const int len = 31 - __clz((int)p);
            if (len >= 9) {
                const uint32_t aIdx = 254u + (p & 255u);
                const int hb = len - 8;
                const uint32_t bIdx = ((1u << hb) - 2u) + ((p >> 8) & ((1u << hb) - 1u));
                const int s = atomicAdd(&cntM, 1);
                metaM[s] = make_uint4(aIdx, bIdx, (uint32_t)((n << 2) | tile), 0);
            } else {
                const uint32_t sIdx = (len >= 1)
                    ? (((1u << len) - 2u) + (p & ((1u << len) - 1u))) : 0xFFFFFFFFu;
                const int s = atomicAdd(&cntC, 1);
                metaC[s] = make_uint4(sIdx, 0, (uint32_t)((n << 2) | tile), 0);
            }
        }
    }
    __syncthreads();

    // copy / identity items
    for (int i = 0; i < cntC; ++i) {
        const uint4 mt4 = metaC[i];
        const int n = (int)(mt4.z >> 2), tile = (int)(mt4.z & 3);
        const int mo = (tile >> 1) * 128, no = (tile & 1) * 128;
        float* C = out + (size_t)n * MATSZ;
        const int r = tid >> 2, cb = (tid & 3) * 32;
        float* d = C + (size_t)(mo + r) * DIM + no + cb;
        if (mt4.x != 0xFFFFFFFFu) {
            const f16* sh = g_tabAh + (size_t)mt4.x * MATSZ + (size_t)(mo + r) * DIM + no + cb;
            #pragma unroll
            for (int j = 0; j < 16; ++j) {
                __half2 h = *(const __half2*)(sh + 2*j);
                *(float2*)(d + 2*j) = make_float2(__half2float(h.x), __half2float(h.y));
            }
        } else {
            #pragma unroll
            for (int j = 0; j < 32; ++j)
                d[j] = ((mo + r) == (no + cb + j)) ? 1.0f : 0.0f;
        }
    }

    const int G = cntM * 8;
    if (G == 0) return;
    const int lr = tid >> 2, cc = tid & 3;
    const uint32_t sd0 = swz((uint32_t)lr, (uint32_t)cc * 16u);
    const size_t rowOffA = (size_t)lr * DIM + cc * 8;

    auto issue = [&](int g) {
        const uint4 mt4 = metaM[g >> 3];
        const int c = g & 7, tile = (int)(mt4.z & 3);
        const int mo = (tile >> 1) * 128, no = (tile & 1) * 128;
        const uint32_t st = smb + (uint32_t)(g & (LDEPTH - 1)) * 16384u;
        const size_t ao = (size_t)mt4.x * MATSZ + (size_t)mo * DIM + rowOffA + c * 32;
        const size_t bo = (size_t)mt4.y * MATSZ + (size_t)no * DIM + rowOffA + c * 32;
        cp16(st + sd0,        g_tabAh + ao);
        cp16(st + sd0 + 8192, g_tabBh + bo);
    };

    float acc[2][4][4];
    #pragma unroll
    for (int mt = 0; mt < 2; ++mt)
        #pragma unroll
        for (int nb = 0; nb < 4; ++nb)
            #pragma unroll
            for (int q = 0; q < 4; ++q) acc[mt][nb][q] = 0.0f;

    #pragma unroll
    for (int p = 0; p < LDEPTH - 2; ++p) {
        if (p < G) issue(p);
        cp_commit();
    }

    for (int g = 0; g < G; g += 2) {
        cp_wait<4>();
        __syncthreads();
        if (g + 6 < G) issue(g + 6);
        cp_commit();
        if (g + 7 < G) issue(g + 7);
        cp_commit();
        const uint32_t st0 = smb + (uint32_t)(g & (LDEPTH - 1)) * 16384u;
        const uint32_t st1 = smb + (uint32_t)((g + 1) & (LDEPTH - 1)) * 16384u;
        mma_chunk<1>(st0, 0, st0 + 8192, 0, lane, m0w, n0w, acc);
        mma_chunk<1>(st1, 0, st1 + 8192, 0, lane, m0w, n0w, acc);

        if (((g + 1) & 7) == 7) {
            const uint4 mt4 = metaM[(g + 1) >> 3];
            const int n = (int)(mt4.z >> 2), tile = (int)(mt4.z & 3);
            const int mo = (tile >> 1) * 128, no = (tile & 1) * 128;
            float* C = out + (size_t)n * MATSZ;
            const int r0 = lane >> 2, cq = (lane & 3) * 2;
            #pragma unroll
            for (int mt = 0; mt < 2; ++mt)
                #pragma unroll
                for (int half = 0; half < 2; ++half) {
                    const int gr = mo + m0w + mt * 16 + r0 + half * 8;
                    #pragma unroll
                    for (int nb = 0; nb < 4; ++nb) {
                        const int gc = no + n0w + nb * 8 + cq;
                        *(float2*)(C + (size_t)gr * DIM + gc) =
                            make_float2(acc[mt][nb][half * 2], acc[mt][nb][half * 2 + 1]);
                        acc[mt][nb][half * 2] = 0.0f;
                        acc[mt][nb][half * 2 + 1] = 0.0f;
                    }
                }
        }
    }
}

// ---------------- host orchestration -----------------------------------------
extern "C" void kernel_launch(void* const* d_in, const int* in_sizes, int n_in,
                              void* d_out, int out_size)
{
    const float* prim   = (const float*)d_in[0];
    const int*   unique = (const int*)d_in[2];
    float*       out    = (float*)d_out;
    (void)in_sizes; (void)n_in; (void)out_size;

    cudaFuncSetAttribute(k_gemm_split, cudaFuncAttributeMaxDynamicSharedMemorySize, SM_EXPM);
    cudaFuncSetAttribute(k_tab<1>, cudaFuncAttributeMaxDynamicSharedMemorySize, SM_TAB1);
    cudaFuncSetAttribute(k_tab<2>, cudaFuncAttributeMaxDynamicSharedMemorySize, SM_TAB2);
    cudaFuncSetAttribute(k_leaf,   cudaFuncAttributeMaxDynamicSharedMemorySize, SM_LEAF);

    f16 *eAh, *eAl, *TAh, *TAl, *TBh, *TBl, *tAh, *tBh, *tBl;
    cudaGetSymbolAddress((void**)&eAh, g_eAh);
    cudaGetSymbolAddress((void**)&eAl, g_eAl);
    cudaGetSymbolAddress((void**)&TAh, g_TAh);
    cudaGetSymbolAddress((void**)&TAl, g_TAl);
    cudaGetSymbolAddress((void**)&TBh, g_TBh);
    cudaGetSymbolAddress((void**)&TBl, g_TBl);
    cudaGetSymbolAddress((void**)&tAh, g_tabAh);
    cudaGetSymbolAddress((void**)&tBh, g_tabBh);
    cudaGetSymbolAddress((void**)&tBl, g_tabBl);

    auto TA_h = [&](int i) { return TAh + (size_t)i * 2 * MATSZ; };
    auto TA_l = [&](int i) { return TAl + (size_t)i * 2 * MATSZ; };
    auto TB_h = [&](int i) { return TBh + (size_t)i * 2 * MATSZ; };
    auto TB_l = [&](int i) { return TBl + (size_t)i * 2 * MATSZ; };

    const dim3 gE(2, 8, 2);

    k_skew<<<(2 * MATSZ + 255) / 256, 256>>>(prim, TB_h(0), TB_l(0));

    // Horner k=3..1 (Taylor degree 4)
    int cur = 0;
    for (int k = 3; k >= 1; --k) {
        const int nxt = cur ^ 1;
        const bool last = (k == 1);
        k_gemm_split<<<gE, 128, SM_EXPM>>>(
            eAh, eAl, TB_h(cur), TB_l(cur),
            last ? TA_h(nxt) : nullptr, last ? TA_l(nxt) : nullptr,
            TB_h(nxt), TB_l(nxt), 1.0f / (float)k, 1);
        cur = nxt;
    }
    // 4 squarings; last lands in table level-1 slots
    for (int sq = 0; sq < 4; ++sq) {
        const int nxt = cur ^ 1;
        const bool last = (sq == 3);
        k_gemm_split<<<gE, 128, SM_EXPM>>>(
            TA_h(cur), TA_l(cur), TB_h(cur), TB_l(cur),
            last ? tAh : TA_h(nxt), last ? nullptr : TA_l(nxt),
            last ? tBh : TB_h(nxt), last ? tBl : TB_l(nxt), 1.0f, 0);
        cur = nxt;
    }

    // tables: levels 2-4 with MW=1 (32-row tiles, better fill), 5-8 with MW=2
    for (int lvl = 2; lvl <= 4; ++lvl)
        k_tab<1><<<dim3(2, 8, 1 << lvl), 128, SM_TAB1>>>(lvl);
    for (int lvl = 5; lvl <= 8; ++lvl)
        k_tab<2><<<dim3(2, 4, 1 << lvl), 256, SM_TAB2>>>(lvl);

    k_leaf<<<PGRID, 512, SM_LEAF>>>(unique, out);
}

// round 14
// speedup vs baseline: 1.6471x; 1.6471x over previous
#include <cuda_runtime.h>
#include <cuda_fp16.h>
#include <cstdint>

#define DIM 256
#define MATSZ (DIM*DIM)
#define NPOS 2048
#define NITEMS (NPOS*4)
#define PGRID 148
#define DEPTH 4
#define LDEPTH 8
#define BT 8192                 // B tile: 128 rows * 64B
#define PITCH 129

#define SM_EXPM  (DEPTH*20480)           // MW=1,NPROD=3: 2*2048 + 2*8192
#define SM_TAB1  (DEPTH*18432)           // MW=1,NPROD=2: 2048 + 2*8192
#define SM_TAB2  (DEPTH*20480)           // MW=2,NPROD=2: 4096 + 2*8192
#define SM_LEAF  (LDEPTH*16384 + 2048)   // stages + meta

using f16 = __half;

// ---------------- static device scratch --------------------------------------
__device__ f16 g_eAh[2*MATSZ], g_eAl[2*MATSZ];
__device__ f16 g_TAh[2][2*MATSZ], g_TAl[2][2*MATSZ];
__device__ f16 g_TBh[2][2*MATSZ], g_TBl[2][2*MATSZ];
__device__ f16 g_tabAh[510*MATSZ];                     // A-layout hi (all levels)
__device__ f16 g_tabBh[510*MATSZ], g_tabBl[510*MATSZ]; // B-layout; lo used only lvl-1

// ---------------- helpers -----------------------------------------------------
__device__ __forceinline__ uint32_t smem_u32(const void* p) {
    uint32_t a;
    asm("{ .reg .u64 t; cvta.to.shared.u64 t, %1; cvt.u32.u64 %0, t; }" : "=r"(a) : "l"(p));
    return a;
}
__device__ __forceinline__ void ldm4(uint32_t a[4], uint32_t addr) {
    asm volatile("ldmatrix.sync.aligned.m8n8.x4.shared.b16 {%0,%1,%2,%3}, [%4];"
                 : "=r"(a[0]), "=r"(a[1]), "=r"(a[2]), "=r"(a[3]) : "r"(addr));
}
__device__ __forceinline__ void mma16816(float c[4], const uint32_t a[4],
                                         uint32_t b0, uint32_t b1) {
    asm volatile("mma.sync.aligned.m16n8k16.row.col.f32.f16.f16.f32 "
                 "{%0,%1,%2,%3}, {%4,%5,%6,%7}, {%8,%9}, {%0,%1,%2,%3};"
                 : "+f"(c[0]), "+f"(c[1]), "+f"(c[2]), "+f"(c[3])
                 : "r"(a[0]), "r"(a[1]), "r"(a[2]), "r"(a[3]), "r"(b0), "r"(b1));
}
__device__ __forceinline__ void cp16(uint32_t s, const void* g) {
    asm volatile("cp.async.cg.shared.global [%0], [%1], 16;" :: "r"(s), "l"(g));
}
__device__ __forceinline__ void cp_commit() {
    asm volatile("cp.async.commit_group;" ::: "memory");
}
template<int N>
__device__ __forceinline__ void cp_wait() {
    asm volatile("cp.async.wait_group %0;" :: "n"(N) : "memory");
}
__device__ __forceinline__ uint32_t swz(uint32_t row, uint32_t byteInRow) {
    uint32_t chunk = byteInRow >> 4;
    return row * 64u + ((chunk ^ ((row >> 1) & 3u)) << 4) + (byteInRow & 15u);
}
__device__ __forceinline__ uint32_t pack_hi(float f0, float f1, uint32_t& lo) {
    f16 h0 = __float2half(f0), h1 = __float2half(f1);
    f16 l0 = __float2half(f0 - __half2float(h0));
    f16 l1 = __float2half(f1 - __half2float(h1));
    __half2 hh = __halves2half2(h0, h1);
    __half2 ll = __halves2half2(l0, l1);
    lo = *(uint32_t*)&ll;
    return *(uint32_t*)&hh;
}

// ---------------- templated chunk MMA ----------------------------------------
template<int NPROD>
__device__ __forceinline__ void mma_chunk(uint32_t aBase, uint32_t aLo,
                                          uint32_t bBase, uint32_t bLo,
                                          int lane, int m0w, int n0w, float acc[2][4][4])
{
    #pragma unroll
    for (int s = 0; s < 2; ++s) {
        uint32_t ah[2][4], al[2][4], bh[2][4], bl[2][4];
        #pragma unroll
        for (int mt = 0; mt < 2; ++mt) {
            const uint32_t off = swz((uint32_t)(m0w + mt * 16 + (lane & 15)),
                                     (uint32_t)(s * 32 + ((lane & 16) ? 16 : 0)));
            ldm4(ah[mt], aBase + off);
            if (NPROD == 3) ldm4(al[mt], aLo + off);
        }
        #pragma unroll
        for (int nt = 0; nt < 2; ++nt) {
            const uint32_t off = swz((uint32_t)(n0w + nt * 16 + (lane & 7) + ((lane & 16) ? 8 : 0)),
                                     (uint32_t)(s * 32 + ((lane & 8) ? 16 : 0)));
            ldm4(bh[nt], bBase + off);
            if (NPROD >= 2) ldm4(bl[nt], bLo + off);
        }
        #pragma unroll
        for (int mt = 0; mt < 2; ++mt)
            #pragma unroll
            for (int nb = 0; nb < 4; ++nb) {
                const uint32_t b0h = bh[nb >> 1][(nb & 1) * 2];
                const uint32_t b1h = bh[nb >> 1][(nb & 1) * 2 + 1];
                mma16816(acc[mt][nb], ah[mt], b0h, b1h);
                if (NPROD >= 2)
                    mma16816(acc[mt][nb], ah[mt],
                             bl[nb >> 1][(nb & 1) * 2], bl[nb >> 1][(nb & 1) * 2 + 1]);
                if (NPROD == 3)
                    mma16816(acc[mt][nb], al[mt], b0h, b1h);
            }
    }
}

// ---------------- templated pipelined GEMM ------------------------------------
template<int MW, int NPROD>
__device__ __forceinline__ void gemm_run(
    const f16* __restrict__ Ah, const f16* __restrict__ Al,
    const f16* __restrict__ Bh, const f16* __restrict__ Bl,
    float acc[2][4][4])
{
    constexpr int MTILE  = 32 * MW;
    constexpr int NTHR   = 128 * MW;
    constexpr int ATILEB = MTILE * 64;
    constexpr int NA = (NPROD == 3) ? 2 : 1;
    constexpr int NB = (NPROD >= 2) ? 2 : 1;
    constexpr uint32_t STG = (uint32_t)(NA * ATILEB + NB * BT);

    extern __shared__ char sm[];
    const uint32_t smb = smem_u32(sm);
    const int tid = threadIdx.x, lane = tid & 31, wid = tid >> 5;
    const int m0w = (wid % MW) * 32, n0w = (wid / MW) * 32;
    const int lr = tid >> 2, cc = tid & 3;
    const uint32_t sdr = swz((uint32_t)lr, (uint32_t)cc * 16u);

    #pragma unroll
    for (int mt = 0; mt < 2; ++mt)
        #pragma unroll
        for (int nb = 0; nb < 4; ++nb)
            #pragma unroll
            for (int q = 0; q < 4; ++q) acc[mt][nb][q] = 0.0f;

    auto issue = [&](int c) {
        const uint32_t st = smb + (uint32_t)(c & (DEPTH - 1)) * STG;
        {
            const size_t go = (size_t)lr * DIM + c * 32 + cc * 8;
            cp16(st + sdr, Ah + go);
            if (NPROD == 3) cp16(st + sdr + ATILEB, Al + go);
        }
        #pragma unroll
        for (int rr = 0; rr < 128; rr += NTHR / 4) {
            const int r = lr + rr;
            const uint32_t sd = st + (uint32_t)(NA * ATILEB) + swz((uint32_t)r, (uint32_t)cc * 16u);
            const size_t go = (size_t)r * DIM + c * 32 + cc * 8;
            cp16(sd, Bh + go);
            if (NPROD >= 2) cp16(sd + BT, Bl + go);
        }
    };

    #pragma unroll
    for (int p = 0; p < DEPTH - 1; ++p) { issue(p); cp_commit(); }

    for (int c = 0; c < 8; ++c) {
        cp_wait<DEPTH - 2>();
        __syncthreads();
        if (c + DEPTH - 1 < 8) issue(c + DEPTH - 1);
        cp_commit();
        const uint32_t st = smb + (uint32_t)(c & (DEPTH - 1)) * STG;
        mma_chunk<NPROD>(st, st + ATILEB, st + NA * ATILEB, st + NA * ATILEB + BT,
                         lane, m0w, n0w, acc);
    }
}

// ---------------- templated staged epilogue -----------------------------------
template<int MW>
__device__ __forceinline__ void epi_split(float acc[2][4][4], float alpha, int addI,
                                          int mo, int no,
                                          f16* __restrict__ oAh, f16* __restrict__ oAl,
                                          f16* __restrict__ oBh, f16* __restrict__ oBl)
{
    extern __shared__ char sm[];
    float* sf = (float*)sm;
    const int tid = threadIdx.x, lane = tid & 31, wid = tid >> 5;
    const int m0w = (wid % MW) * 32, n0w = (wid / MW) * 32;
    const int r0 = lane >> 2, cq = (lane & 3) * 2;

    __syncthreads();
    #pragma unroll
    for (int mt = 0; mt < 2; ++mt)
        #pragma unroll
        for (int half = 0; half < 2; ++half) {
            const int row = m0w + mt * 16 + r0 + half * 8;
            const int gr = mo + row;
            #pragma unroll
            for (int nb = 0; nb < 4; ++nb) {
                const int col = n0w + nb * 8 + cq;
                const int gc = no + col;
                float v0 = alpha * acc[mt][nb][half * 2 + 0];
                float v1 = alpha * acc[mt][nb][half * 2 + 1];
                if (addI) {
                    if (gr == gc)     v0 += 1.0f;
                    if (gr == gc + 1) v1 += 1.0f;
                }
                sf[row * PITCH + col]     = v0;
                sf[row * PITCH + col + 1] = v1;
            }
        }
    __syncthreads();

    if (oAh) {
        const int r = tid >> 2, c0 = (tid & 3) * 32;
        uint32_t hv[16], lv[16];
        #pragma unroll
        for (int j = 0; j < 16; ++j)
            hv[j] = pack_hi(sf[r * PITCH + c0 + 2*j], sf[r * PITCH + c0 + 2*j + 1], lv[j]);
        uint4* dh = (uint4*)(oAh + (size_t)(mo + r) * DIM + no + c0);
        #pragma unroll
        for (int q = 0; q < 4; ++q)
            dh[q] = make_uint4(hv[4*q], hv[4*q+1], hv[4*q+2], hv[4*q+3]);
        if (oAl) {
            uint4* dl = (uint4*)(oAl + (size_t)(mo + r) * DIM + no + c0);
            #pragma unroll
            for (int q = 0; q < 4; ++q)
                dl[q] = make_uint4(lv[4*q], lv[4*q+1], lv[4*q+2], lv[4*q+3]);
        }
    }
    {
        const int c = tid & 127, rg = tid >> 7;
        const int rb = rg * 32;
        uint32_t hv[16], lv[16];
        #pragma unroll
        for (int j = 0; j < 16; ++j)
            hv[j] = pack_hi(sf[(rb + 2*j) * PITCH + c], sf[(rb + 2*j + 1) * PITCH + c], lv[j]);
        uint4* dh = (uint4*)(oBh + (size_t)(no + c) * DIM + mo + rb);
        #pragma unroll
        for (int q = 0; q < 4; ++q)
            dh[q] = make_uint4(hv[4*q], hv[4*q+1], hv[4*q+2], hv[4*q+3]);
        if (oBl) {
            uint4* dl = (uint4*)(oBl + (size_t)(no + c) * DIM + mo + rb);
            #pragma unroll
            for (int q = 0; q < 4; ++q)
                dl[q] = make_uint4(lv[4*q], lv[4*q+1], lv[4*q+2], lv[4*q+3]);
        }
    }
    __syncthreads();
}

// ---------------- kernels -----------------------------------------------------
// A = skew^T/16 ; seed T = I + A/4 (Taylor d=4, 4 squarings)
__global__ void k_skew(const float* __restrict__ prim, f16* TBh, f16* TBl)
{
    int idx = blockIdx.x * blockDim.x + threadIdx.x;
    if (idx >= 2 * MATSZ) return;
    int b = idx >> 16, ij = idx & 65535, i = ij >> 8, j = ij & 255;
    float a = (prim[(size_t)b * MATSZ + (size_t)j * DIM + i] -
               prim[(size_t)b * MATSZ + (size_t)i * DIM + j]) * 0.0625f;
    f16 h = __float2half(a);
    g_eAh[idx] = h;
    g_eAl[idx] = __float2half(a - __half2float(h));
    float d = (i == j) ? 1.0f : 0.0f;
    float tb = d - a * 0.25f;
    f16 th = __float2half(tb);
    TBh[idx] = th;
    TBl[idx] = __float2half(tb - __half2float(th));
}

// expm round: MW=1, NPROD=3. grid (2, 8, 2), block 128.
__global__ __launch_bounds__(128, 1)
void k_gemm_split(const f16* Ah, const f16* Al, const f16* Bh, const f16* Bl,
                  f16* oAh, f16* oAl, f16* oBh, f16* oBl, float alpha, int addI)
{
    const size_t off = (size_t)blockIdx.z * MATSZ;
    const int mo = blockIdx.y * 32, no = blockIdx.x * 128;
    float acc[2][4][4];
    gemm_run<1, 3>(Ah + off + (size_t)mo * DIM, Al + off + (size_t)mo * DIM,
                   Bh + off + (size_t)no * DIM, Bl + off + (size_t)no * DIM, acc);
    epi_split<1>(acc, alpha, addI, mo, no,
                 oAh ? oAh + off : nullptr, oAl ? oAl + off : nullptr,
                 oBh + off, oBl ? oBl + off : nullptr);
}

// table level build: NPROD=2 (A hi only, B = parent split), MW templated.
template<int MW>
__global__ __launch_bounds__(128 * MW, (MW == 1) ? 4 : 2)
void k_tab(int lvl)
{
    const int c = blockIdx.z;
    const int lb = lvl - 1;
    const size_t aoff = (size_t)(((1 << lb) - 2) + (c & ((1 << lb) - 1))) * MATSZ;
    const size_t boff = (size_t)(c >> lb) * MATSZ;
    const size_t ooff = (size_t)(((1 << lvl) - 2) + c) * MATSZ;
    const int mo = blockIdx.y * (32 * MW), no = blockIdx.x * 128;
    float acc[2][4][4];
    gemm_run<MW, 2>(g_tabAh + aoff + (size_t)mo * DIM, nullptr,
                    g_tabBh + boff + (size_t)no * DIM,
                    g_tabBl + boff + (size_t)no * DIM, acc);
    epi_split<MW>(acc, 1.0f, 0, mo, no,
                  g_tabAh + ooff, nullptr, g_tabBh + ooff, nullptr);
}

// ---------------- persistent leaf kernel (1-product, DEPTH=LDEPTH) ------------
__global__ __launch_bounds__(512, 1)
void k_leaf(const int* __restrict__ unique, float* __restrict__ out)
{
    extern __shared__ char sm[];
    const uint32_t smb = smem_u32(sm);
    uint4* metaM = (uint4*)(sm + LDEPTH * 16384);
    uint4* metaC = metaM + 60;
    __shared__ int cntM, cntC;
    const int tid = threadIdx.x, lane = tid & 31, wid = tid >> 5;
    const int m0w = (wid & 3) * 32, n0w = (wid >> 2) * 32;
    const int bid = blockIdx.x;

    if (tid == 0) { cntM = 0; cntC = 0; }
    __syncthreads();

    {
        const int w = bid + tid * PGRID;
        if (w < NITEMS) {
            const int n = w >> 2, tile = w & 3;
            const unsigned p = (unsigned)unique[n];
            const int len = 31 - __clz((int)p);
            if (len >= 9) {
                const uint32_t aIdx = 254u + (p & 255u);
                const int hb = len - 8;
                const uint32_t bIdx = ((1u << hb) - 2u) + ((p >> 8) & ((1u << hb) - 1u));
                const int s = atomicAdd(&cntM, 1);
                metaM[s] = make_uint4(aIdx, bIdx, (uint32_t)((n << 2) | tile), 0);
            } else {
                const uint32_t sIdx = (len >= 1)
                    ? (((1u << len) - 2u) + (p & ((1u << len) - 1u))) : 0xFFFFFFFFu;
                const int s = atomicAdd(&cntC, 1);
                metaC[s] = make_uint4(sIdx, 0, (uint32_t)((n << 2) | tile), 0);
            }
        }
    }
    __syncthreads();

    // copy / identity items
    for (int i = 0; i < cntC; ++i) {
        const uint4 mt4 = metaC[i];
        const int n = (int)(mt4.z >> 2), tile = (int)(mt4.z & 3);
        const int mo = (tile >> 1) * 128, no = (tile & 1) * 128;
        float* C = out + (size_t)n * MATSZ;
        const int r = tid >> 2, cb = (tid & 3) * 32;
        float* d = C + (size_t)(mo + r) * DIM + no + cb;
        if (mt4.x != 0xFFFFFFFFu) {
            const f16* sh = g_tabAh + (size_t)mt4.x * MATSZ + (size_t)(mo + r) * DIM + no + cb;
            #pragma unroll
            for (int j = 0; j < 16; ++j) {
                __half2 h = *(const __half2*)(sh + 2*j);
                *(float2*)(d + 2*j) = make_float2(__half2float(h.x), __half2float(h.y));
            }
        } else {
            #pragma unroll
            for (int j = 0; j < 32; ++j)
                d[j] = ((mo + r) == (no + cb + j)) ? 1.0f : 0.0f;
        }
    }

    const int G = cntM * 8;
    if (G == 0) return;
    const int lr = tid >> 2, cc = tid & 3;
    const uint32_t sd0 = swz((uint32_t)lr, (uint32_t)cc * 16u);
    const size_t rowOffA = (size_t)lr * DIM + cc * 8;

    auto issue = [&](int g) {
        const uint4 mt4 = metaM[g >> 3];
        const int c = g & 7, tile = (int)(mt4.z & 3);
        const int mo = (tile >> 1) * 128, no = (tile & 1) * 128;
        const uint32_t st = smb + (uint32_t)(g & (LDEPTH - 1)) * 16384u;
        const size_t ao = (size_t)mt4.x * MATSZ + (size_t)mo * DIM + rowOffA + c * 32;
        const size_t bo = (size_t)mt4.y * MATSZ + (size_t)no * DIM + rowOffA + c * 32;
        cp16(st + sd0,        g_tabAh + ao);
        cp16(st + sd0 + 8192, g_tabBh + bo);
    };

    float acc[2][4][4];
    #pragma unroll
    for (int mt = 0; mt < 2; ++mt)
        #pragma unroll
        for (int nb = 0; nb < 4; ++nb)
            #pragma unroll
            for (int q = 0; q < 4; ++q) acc[mt][nb][q] = 0.0f;

    #pragma unroll
    for (int p = 0; p < LDEPTH - 1; ++p) {
        if (p < G) issue(p);
        cp_commit();
    }

    for (int g = 0; g < G; ++g) {
        cp_wait<LDEPTH - 2>();
        __syncthreads();
        if (g + LDEPTH - 1 < G) issue(g + LDEPTH - 1);
        cp_commit();
        const uint32_t st = smb + (uint32_t)(g & (LDEPTH - 1)) * 16384u;
        mma_chunk<1>(st, 0, st + 8192, 0, lane, m0w, n0w, acc);

        if ((g & 7) == 7) {
            const uint4 mt4 = metaM[g >> 3];
            const int n = (int)(mt4.z >> 2), tile = (int)(mt4.z & 3);
            const int mo = (tile >> 1) * 128, no = (tile & 1) * 128;
            float* C = out + (size_t)n * MATSZ;
            const int r0 = lane >> 2, cq = (lane & 3) * 2;
            #pragma unroll
            for (int mt = 0; mt < 2; ++mt)
                #pragma unroll
                for (int half = 0; half < 2; ++half) {
                    const int gr = mo + m0w + mt * 16 + r0 + half * 8;
                    #pragma unroll
                    for (int nb = 0; nb < 4; ++nb) {
                        const int gc = no + n0w + nb * 8 + cq;
                        *(float2*)(C + (size_t)gr * DIM + gc) =
                            make_float2(acc[mt][nb][half * 2], acc[mt][nb][half * 2 + 1]);
                        acc[mt][nb][half * 2] = 0.0f;
                        acc[mt][nb][half * 2 + 1] = 0.0f;
                    }
                }
        }
    }
}

// ---------------- host orchestration -----------------------------------------
extern "C" void kernel_launch(void* const* d_in, const int* in_sizes, int n_in,
                              void* d_out, int out_size)
{
    const float* prim   = (const float*)d_in[0];
    const int*   unique = (const int*)d_in[2];
    float*       out    = (float*)d_out;
    (void)in_sizes; (void)n_in; (void)out_size;

    cudaFuncSetAttribute(k_gemm_split, cudaFuncAttributeMaxDynamicSharedMemorySize, SM_EXPM);
    cudaFuncSetAttribute(k_tab<1>, cudaFuncAttributeMaxDynamicSharedMemorySize, SM_TAB1);
    cudaFuncSetAttribute(k_tab<2>, cudaFuncAttributeMaxDynamicSharedMemorySize, SM_TAB2);
    cudaFuncSetAttribute(k_leaf,   cudaFuncAttributeMaxDynamicSharedMemorySize, SM_LEAF);

    f16 *eAh, *eAl, *TAh, *TAl, *TBh, *TBl, *tAh, *tBh, *tBl;
    cudaGetSymbolAddress((void**)&eAh, g_eAh);
    cudaGetSymbolAddress((void**)&eAl, g_eAl);
    cudaGetSymbolAddress((void**)&TAh, g_TAh);
    cudaGetSymbolAddress((void**)&TAl, g_TAl);
    cudaGetSymbolAddress((void**)&TBh, g_TBh);
    cudaGetSymbolAddress((void**)&TBl, g_TBl);
    cudaGetSymbolAddress((void**)&tAh, g_tabAh);
    cudaGetSymbolAddress((void**)&tBh, g_tabBh);
    cudaGetSymbolAddress((void**)&tBl, g_tabBl);

    auto TA_h = [&](int i) { return TAh + (size_t)i * 2 * MATSZ; };
    auto TA_l = [&](int i) { return TAl + (size_t)i * 2 * MATSZ; };
    auto TB_h = [&](int i) { return TBh + (size_t)i * 2 * MATSZ; };
    auto TB_l = [&](int i) { return TBl + (size_t)i * 2 * MATSZ; };

    const dim3 gE(2, 8, 2);

    k_skew<<<(2 * MATSZ + 255) / 256, 256>>>(prim, TB_h(0), TB_l(0));

    // Horner k=3..1 (Taylor degree 4)
    int cur = 0;
    for (int k = 3; k >= 1; --k) {
        const int nxt = cur ^ 1;
        const bool last = (k == 1);
        k_gemm_split<<<gE, 128, SM_EXPM>>>(
            eAh, eAl, TB_h(cur), TB_l(cur),
            last ? TA_h(nxt) : nullptr, last ? TA_l(nxt) : nullptr,
            TB_h(nxt), TB_l(nxt), 1.0f / (float)k, 1);
        cur = nxt;
    }
    // 4 squarings; last lands in table level-1 slots
    for (int sq = 0; sq < 4; ++sq) {
        const int nxt = cur ^ 1;
        const bool last = (sq == 3);
        k_gemm_split<<<gE, 128, SM_EXPM>>>(
            TA_h(cur), TA_l(cur), TB_h(cur), TB_l(cur),
            last ? tAh : TA_h(nxt), last ? nullptr : TA_l(nxt),
            last ? tBh : TB_h(nxt), last ? tBl : TB_l(nxt), 1.0f, 0);
        cur = nxt;
    }

    // tables: levels 2-4 with MW=1 (32-row tiles, better fill), 5-8 with MW=2
    for (int lvl = 2; lvl <= 4; ++lvl)
        k_tab<1><<<dim3(2, 8, 1 << lvl), 128, SM_TAB1>>>(lvl);
    for (int lvl = 5; lvl <= 8; ++lvl)
        k_tab<2><<<dim3(2, 4, 1 << lvl), 256, SM_TAB2>>>(lvl);

    k_leaf<<<PGRID, 512, SM_LEAF>>>(unique, out);
}